// round 9
// baseline (speedup 1.0000x reference)
#include <cuda_runtime.h>
#include <cuda_bf16.h>
#include <cstdint>

#define NB 8
#define C1 256
#define C2 512
#define HW 4096
#define D  64
#define M  1024
#define LOG2E 1.4426950408889634f

// Scratch (device globals: allocation-free rule)
__device__ __align__(16) __nv_bfloat16 g_x2ph[NB * C2 * M];  // pooled x2, bf16
__device__ __align__(16) __nv_bfloat16 g_Qth[NB * D * HW];   // [b][d][n]
__device__ __align__(16) __nv_bfloat16 g_Kth[NB * D * M];    // [b][d][m], pre-scaled by log2e
__device__ __align__(16) __nv_bfloat16 g_Vth[NB * D * M];    // [b][d][m]
__device__ __align__(16) __nv_bfloat16 g_Wkh[D * C2];
__device__ __align__(16) __nv_bfloat16 g_Wvh[D * C2];
__device__ __align__(16) __nv_bfloat16 g_Wqh[D * C1];
__device__ __align__(16) __nv_bfloat16 g_Woh[C1 * D];

__device__ __forceinline__ uint32_t pack_bf16(float a, float b) {
    __nv_bfloat162 h = __floats2bfloat162_rn(a, b);
    return *reinterpret_cast<uint32_t*>(&h);
}
__device__ __forceinline__ float ex2f(float x) {
    float y;
    asm("ex2.approx.f32 %0, %1;" : "=f"(y) : "f"(x));
    return y;
}
__device__ __forceinline__ void ldsm4(uint32_t& r0, uint32_t& r1, uint32_t& r2,
                                      uint32_t& r3, uint32_t addr) {
    asm volatile("ldmatrix.sync.aligned.m8n8.x4.shared.b16 {%0,%1,%2,%3}, [%4];\n"
                 : "=r"(r0), "=r"(r1), "=r"(r2), "=r"(r3) : "r"(addr));
}
__device__ __forceinline__ void ldsm4t(uint32_t& r0, uint32_t& r1, uint32_t& r2,
                                       uint32_t& r3, uint32_t addr) {
    asm volatile("ldmatrix.sync.aligned.m8n8.x4.trans.shared.b16 {%0,%1,%2,%3}, [%4];\n"
                 : "=r"(r0), "=r"(r1), "=r"(r2), "=r"(r3) : "r"(addr));
}
__device__ __forceinline__ void mma16816(float c[4], const uint32_t a[4],
                                         uint32_t b0, uint32_t b1) {
    asm volatile("mma.sync.aligned.m16n8k16.row.col.f32.bf16.bf16.f32 "
                 "{%0,%1,%2,%3}, {%4,%5,%6,%7}, {%8,%9}, {%0,%1,%2,%3};\n"
                 : "+f"(c[0]), "+f"(c[1]), "+f"(c[2]), "+f"(c[3])
                 : "r"(a[0]), "r"(a[1]), "r"(a[2]), "r"(a[3]), "r"(b0), "r"(b1));
}
__device__ __forceinline__ void cp16(uint32_t saddr, const void* g) {
    asm volatile("cp.async.cg.shared.global [%0], [%1], 16;\n" :: "r"(saddr), "l"(g));
}
__device__ __forceinline__ void cp_commit() { asm volatile("cp.async.commit_group;\n"); }
__device__ __forceinline__ void cp_wait0() { asm volatile("cp.async.wait_group 0;\n"); }

// ---------------- kernel A: pool (blocks < 8192) + weight cvt (rest) ----------------
__global__ void prep_kernel(const float* __restrict__ x2,
                            const float* __restrict__ Wk, const float* __restrict__ Wv,
                            const float* __restrict__ Wq, const float* __restrict__ Wo) {
    if (blockIdx.x < 8192) {
        int i = blockIdx.x * 256 + threadIdx.x;
        int j = i & 15, h2 = (i >> 4) & 31, bc = i >> 9;
        const float* s = x2 + ((size_t)bc << 12) + (h2 << 7) + (j << 2);
        float4 f0 = *(const float4*)s;
        float4 f1 = *(const float4*)(s + 64);
        uint32_t p = pack_bf16(0.25f * (f0.x + f0.y + f1.x + f1.y),
                               0.25f * (f0.z + f0.w + f1.z + f1.w));
        *(uint32_t*)(g_x2ph + ((size_t)bc << 10) + (h2 << 5) + (j << 1)) = p;
    } else {
        int i = (blockIdx.x - 8192) * 256 + threadIdx.x;   // 98304 total
        if (i < 32768)      g_Wkh[i] = __float2bfloat16(Wk[i]);
        else if (i < 65536) g_Wvh[i - 32768] = __float2bfloat16(Wv[i - 32768]);
        else if (i < 81920) g_Wqh[i - 65536] = __float2bfloat16(Wq[i - 65536]);
        else                g_Woh[i - 81920] = __float2bfloat16(Wo[i - 81920]);
    }
}

// ---------------- kernel B: K/V projection, 2-stage cp.async pipeline ----------------
__global__ __launch_bounds__(256) void kvproj_kernel(
        const float* __restrict__ bk, const float* __restrict__ bv) {
    __shared__ __align__(16) char smem[49152];  // sX[2][8K] sWk[2][8K] sWv[2][8K]
    const uint32_t s_u = (uint32_t)__cvta_generic_to_shared(smem);

    const int b = blockIdx.y, m0 = blockIdx.x << 6;
    const int tid = threadIdx.x, wid = tid >> 5, lane = tid & 31;
    const int dw = wid & 3, mw = wid >> 2;

    float CK[4][4] = {}, CV[4][4] = {};

    auto issue = [&](int cc, int t) {
        int c0 = cc << 6;
        for (int i = tid; i < 512; i += 256) {
            int r = i >> 3, pos = i & 7;
            uint32_t dst = t * 8192 + r * 128 + ((pos ^ (r & 7)) << 4);
            cp16(s_u + dst,
                 g_x2ph + ((size_t)(b * C2 + c0 + r) << 10) + m0 + (pos << 3));
            cp16(s_u + 16384 + dst, g_Wkh + r * C2 + c0 + (pos << 3));
            cp16(s_u + 32768 + dst, g_Wvh + r * C2 + c0 + (pos << 3));
        }
        cp_commit();
    };

    issue(0, 0);
    for (int cc = 0; cc < 8; cc++) {
        int cur = cc & 1;
        cp_wait0();
        __syncthreads();
        if (cc < 7) issue(cc + 1, cur ^ 1);

        uint32_t sX_u = s_u + cur * 8192;
        uint32_t sWk_u = s_u + 16384 + cur * 8192;
        uint32_t sWv_u = s_u + 32768 + cur * 8192;
#pragma unroll
        for (int ks = 0; ks < 4; ks++) {
            int ar = (dw << 4) + (lane & 15);
            int ag = (ks << 1) + (lane >> 4);
            uint32_t aoff = ar * 128 + ((ag ^ (ar & 7)) << 4);
            uint32_t Ak[4], Av[4];
            ldsm4(Ak[0], Ak[1], Ak[2], Ak[3], sWk_u + aoff);
            ldsm4(Av[0], Av[1], Av[2], Av[3], sWv_u + aoff);
            int krow = (ks << 4) + (lane & 7) + (((lane >> 3) & 1) << 3);
#pragma unroll
            for (int nt = 0; nt < 2; nt++) {
                int ncol = (mw << 5) + (nt << 4) + ((lane >> 4) << 3);
                uint32_t b0, b1, b2, b3;
                ldsm4t(b0, b1, b2, b3,
                       sX_u + krow * 128 + (((ncol >> 3) ^ (krow & 7)) << 4));
                mma16816(CK[2 * nt], Ak, b0, b1);
                mma16816(CK[2 * nt + 1], Ak, b2, b3);
                mma16816(CV[2 * nt], Av, b0, b1);
                mma16816(CV[2 * nt + 1], Av, b2, b3);
            }
        }
    }
    int row0 = (dw << 4) + (lane >> 2);
    float bk0 = bk[row0], bk1 = bk[row0 + 8];
    float bv0 = bv[row0], bv1 = bv[row0 + 8];
    __nv_bfloat16* Kp = g_Kth + ((size_t)b * 64 + row0) * M + m0;
    __nv_bfloat16* Vp = g_Vth + ((size_t)b * 64 + row0) * M + m0;
#pragma unroll
    for (int nt = 0; nt < 2; nt++)
#pragma unroll
        for (int h = 0; h < 2; h++) {
            int ci = 2 * nt + h;
            int ncol = (mw << 5) + (nt << 4) + (h << 3) + ((lane & 3) << 1);
            *(uint32_t*)(Kp + ncol) =
                pack_bf16((CK[ci][0] + bk0) * LOG2E, (CK[ci][1] + bk0) * LOG2E);
            *(uint32_t*)(Kp + (size_t)8 * M + ncol) =
                pack_bf16((CK[ci][2] + bk1) * LOG2E, (CK[ci][3] + bk1) * LOG2E);
            *(uint32_t*)(Vp + ncol) = pack_bf16(CV[ci][0] + bv0, CV[ci][1] + bv0);
            *(uint32_t*)(Vp + (size_t)8 * M + ncol) = pack_bf16(CV[ci][2] + bv1, CV[ci][3] + bv1);
        }
}

// ---------------- kernel C: Q projection, reg-prefetch double buffer ----------------
__global__ __launch_bounds__(256) void qproj_kernel(
        const float* __restrict__ x1, const float* __restrict__ bq) {
    __shared__ __align__(16) char smem[49152];  // sW[4][8K] + sX[2][8K]
    const uint32_t s_u = (uint32_t)__cvta_generic_to_shared(smem);
    const uint32_t sXb_u = s_u + 32768;

    const int b = blockIdx.y, n0 = blockIdx.x << 6;
    const int tid = threadIdx.x, wid = tid >> 5, lane = tid & 31;
    const int dw = wid & 3, mw = wid >> 2;

    for (int i = tid; i < 2048; i += 256) {
        int ch = i >> 9, j = i & 511, r = j >> 3, pos = j & 7;
        cp16(s_u + ch * 8192 + r * 128 + ((pos ^ (r & 7)) << 4),
             g_Wqh + r * C1 + (ch << 6) + (pos << 3));
    }
    cp_commit();

    const int r0 = tid >> 4, p4 = tid & 15;
    const float* xbase = x1 + ((size_t)(b * C1) << 12) + n0 + (p4 << 2);
    float4 f[4];
#pragma unroll
    for (int k = 0; k < 4; k++)
        f[k] = *(const float4*)(xbase + ((size_t)(r0 + 16 * k) << 12));

    float C[4][4] = {};
    const int r7 = r0 & 7;
    const uint32_t sphys = r0 * 128 + (((p4 >> 1) ^ r7) << 4) + ((p4 & 1) << 3);

    for (int cc = 0; cc < 4; cc++) {
        int cur = cc & 1;
        char* xb = smem + 32768 + cur * 8192;
#pragma unroll
        for (int k = 0; k < 4; k++)
            *(uint2*)(xb + sphys + k * 2048) =
                make_uint2(pack_bf16(f[k].x, f[k].y), pack_bf16(f[k].z, f[k].w));
        float4 f2[4];
        if (cc < 3) {
#pragma unroll
            for (int k = 0; k < 4; k++)
                f2[k] = *(const float4*)(xbase +
                         ((size_t)(((cc + 1) << 6) + r0 + 16 * k) << 12));
        }
        if (cc == 0) cp_wait0();
        __syncthreads();

        uint32_t sW_u = s_u + cc * 8192;
        uint32_t sX_u = sXb_u + cur * 8192;
#pragma unroll
        for (int ks = 0; ks < 4; ks++) {
            int ar = (dw << 4) + (lane & 15);
            int ag = (ks << 1) + (lane >> 4);
            uint32_t A[4];
            ldsm4(A[0], A[1], A[2], A[3], sW_u + ar * 128 + ((ag ^ (ar & 7)) << 4));
            int krow = (ks << 4) + (lane & 7) + (((lane >> 3) & 1) << 3);
#pragma unroll
            for (int nt = 0; nt < 2; nt++) {
                int ncol = (mw << 5) + (nt << 4) + ((lane >> 4) << 3);
                uint32_t b0, b1, b2, b3;
                ldsm4t(b0, b1, b2, b3,
                       sX_u + krow * 128 + (((ncol >> 3) ^ (krow & 7)) << 4));
                mma16816(C[2 * nt], A, b0, b1);
                mma16816(C[2 * nt + 1], A, b2, b3);
            }
        }
        if (cc < 3) {
#pragma unroll
            for (int k = 0; k < 4; k++) f[k] = f2[k];
        }
    }
    int row0 = (dw << 4) + (lane >> 2);
    float b0v = bq[row0], b1v = bq[row0 + 8];
    __nv_bfloat16* Qp = g_Qth + ((size_t)b * 64 + row0) * HW + n0;
#pragma unroll
    for (int nt = 0; nt < 2; nt++)
#pragma unroll
        for (int h = 0; h < 2; h++) {
            int ci = 2 * nt + h;
            int ncol = (mw << 5) + (nt << 4) + (h << 3) + ((lane & 3) << 1);
            *(uint32_t*)(Qp + ncol) = pack_bf16(C[ci][0] + b0v, C[ci][1] + b0v);
            *(uint32_t*)(Qp + (size_t)8 * HW + ncol) = pack_bf16(C[ci][2] + b1v, C[ci][3] + b1v);
        }
}

// ---------------- kernel D: key-split attention + out-proj + residual ----------------
// CTA: 64 queries, 4 warps. Warps {0,1}: even key tiles; {2,3}: odd key tiles.
// Each warp: 32 queries (2 m16 frags). 8 loop iterations of a 128-key tile pair.
// Smem (73728 B):
//   stages: stage s at s*32768: [Ke 8K][Ve 8K][Ko 8K][Vo 8K]
//   Q staging at 65536 (8K, [64d][64q])
//   phase B: Wo at [0,32K) (prefetched into stage0 during last iter);
//            sYa at 32768 (64*68*4), sYb at 32768+17408  (also the O-combine bufs)
#define SM_ATTN 73728
__global__ __launch_bounds__(128, 3) void attn_kernel(
        const float* __restrict__ x1, const float* __restrict__ bo,
        float* __restrict__ out) {
    extern __shared__ char sm[];
    const int b = blockIdx.y, n0 = blockIdx.x << 6;
    const int tid = threadIdx.x, wid = tid >> 5, lane = tid & 31;
    const int qw = wid & 1, grp = wid >> 1;
    const uint32_t sm_u = (uint32_t)__cvta_generic_to_shared(sm);

    const __nv_bfloat16* Qg = g_Qth + (size_t)b * 64 * HW + n0;
    const __nv_bfloat16* Kg0 = g_Kth + (size_t)b * 64 * M;
    const __nv_bfloat16* Vg0 = g_Vth + (size_t)b * 64 * M;

    // ---- stage Q [64d][64q] + tile pair 0 into stage 0 ----
    for (int i = tid; i < 512; i += 128) {
        int r = i >> 3, pos = i & 7;
        cp16(sm_u + 65536 + r * 128 + ((pos ^ (r & 7)) << 4),
             Qg + (size_t)r * HW + (pos << 3));
    }
    for (int i = tid; i < 2048; i += 128) {
        int quad = i >> 9, r = (i >> 3) & 63, pos = i & 7;
        uint32_t dst = quad * 8192 + r * 128 + ((pos ^ (r & 7)) << 4);
        const __nv_bfloat16* base = (quad & 1) ? Vg0 : Kg0;
        cp16(sm_u + dst, base + ((quad >> 1) << 6) + (size_t)r * M + (pos << 3));
    }
    cp_commit(); cp_wait0();
    __syncthreads();

    // ---- Q fragments (A-operand), 2 m16 blocks per warp ----
    uint32_t Qf[2][4][4];
#pragma unroll
    for (int h = 0; h < 2; h++) {
        int mcol = (qw << 5) + (h << 4) + (((lane >> 3) & 1) << 3);
#pragma unroll
        for (int s = 0; s < 4; s++) {
            int krow = (s << 4) + (lane & 7) + ((lane >> 4) << 3);
            ldsm4t(Qf[h][s][0], Qf[h][s][1], Qf[h][s][2], Qf[h][s][3],
                   sm_u + 65536 + krow * 128 + (((mcol >> 3) ^ (krow & 7)) << 4));
        }
    }

    float O[2][8][4] = {};
    float l0[2] = {}, l1[2] = {};

    const int brow = (lane & 7) + ((lane >> 4) << 3);
    const int bgsel = (lane >> 3) & 1;
    const int tkrow = (lane & 7) + (((lane >> 3) & 1) << 3);
    const int tnsel = (lane >> 4) << 3;

    for (int it = 0; it < 8; it++) {
        uint32_t cb = sm_u + ((it & 1) << 15) + (grp << 14);   // this group's tile
        // prefetch next pair (or Wo on the last iteration into dead stage 0)
        if (it < 7) {
            uint32_t pb = sm_u + (((it + 1) & 1) << 15);
            int k0 = (it + 1) << 7;
            for (int i = tid; i < 2048; i += 128) {
                int quad = i >> 9, r = (i >> 3) & 63, pos = i & 7;
                uint32_t dst = pb + quad * 8192 + r * 128 + ((pos ^ (r & 7)) << 4);
                const __nv_bfloat16* base = (quad & 1) ? Vg0 : Kg0;
                cp16(dst, base + k0 + ((quad >> 1) << 6) + (size_t)r * M + (pos << 3));
            }
        } else {
            for (int i = tid; i < 2048; i += 128) {
                int rr = i >> 3, pos = i & 7;
                cp16(sm_u + rr * 128 + ((pos ^ (rr & 7)) << 4),
                     g_Woh + rr * 64 + (pos << 3));
            }
        }
        cp_commit();

        // ---- S = Q K^T in two 32-key halves (keeps live S at 32 regs) ----
        uint32_t Pf[2][4][4];
#pragma unroll
        for (int half = 0; half < 2; half++) {
            float S[2][4][4] = {};
#pragma unroll
            for (int s = 0; s < 4; s++) {
                int krow = (s << 4) + tkrow;
                uint32_t rb = cb + krow * 128;
                int r7x = krow & 7;
#pragma unroll
                for (int nh2 = 0; nh2 < 2; nh2++) {
                    int ncol = ((half * 2 + nh2) << 4) + tnsel;
                    uint32_t b0, b1, b2, b3;
                    ldsm4t(b0, b1, b2, b3, rb + (((ncol >> 3) ^ r7x) << 4));
#pragma unroll
                    for (int h = 0; h < 2; h++) {
                        mma16816(S[h][2 * nh2], Qf[h][s], b0, b1);
                        mma16816(S[h][2 * nh2 + 1], Qf[h][s], b2, b3);
                    }
                }
            }
#pragma unroll
            for (int h = 0; h < 2; h++) {
#pragma unroll
                for (int nt = 0; nt < 4; nt++) {
#pragma unroll
                    for (int j = 0; j < 4; j++) S[h][nt][j] = ex2f(S[h][nt][j]);
                    l0[h] += S[h][nt][0] + S[h][nt][1];
                    l1[h] += S[h][nt][2] + S[h][nt][3];
                }
#pragma unroll
                for (int kk = 0; kk < 2; kk++) {
                    Pf[h][half * 2 + kk][0] = pack_bf16(S[h][2 * kk][0], S[h][2 * kk][1]);
                    Pf[h][half * 2 + kk][1] = pack_bf16(S[h][2 * kk][2], S[h][2 * kk][3]);
                    Pf[h][half * 2 + kk][2] = pack_bf16(S[h][2 * kk + 1][0], S[h][2 * kk + 1][1]);
                    Pf[h][half * 2 + kk][3] = pack_bf16(S[h][2 * kk + 1][2], S[h][2 * kk + 1][3]);
                }
            }
        }
        // ---- O += P V ----
        uint32_t vbase = cb + 8192;
#pragma unroll
        for (int kk = 0; kk < 4; kk++) {
#pragma unroll
            for (int dh = 0; dh < 4; dh++) {
                int r = (dh << 4) + brow;
                int g = (kk << 1) + bgsel;
                uint32_t b0, b1, b2, b3;
                ldsm4(b0, b1, b2, b3, vbase + r * 128 + ((g ^ (r & 7)) << 4));
#pragma unroll
                for (int h = 0; h < 2; h++) {
                    mma16816(O[h][2 * dh], Pf[h][kk], b0, b1);
                    mma16816(O[h][2 * dh + 1], Pf[h][kk], b2, b3);
                }
            }
        }
        cp_wait0();
        __syncthreads();
    }

    // ---- combine partial (O, l) across the two key groups ----
    {
        float* cbuf = (float*)(sm + 32768 + grp * 17408) + (tid & 63) * 68;
#pragma unroll
        for (int i = 0; i < 16; i++)
            ((float4*)cbuf)[i] = ((float4*)O)[i];
        cbuf[64] = l0[0]; cbuf[65] = l0[1]; cbuf[66] = l1[0]; cbuf[67] = l1[1];
        __syncthreads();
        const float* obuf = (float*)(sm + 32768 + (grp ^ 1) * 17408) + (tid & 63) * 68;
#pragma unroll
        for (int i = 0; i < 64; i++) ((float*)O)[i] += obuf[i];
        l0[0] += obuf[64]; l0[1] += obuf[65]; l1[0] += obuf[66]; l1[1] += obuf[67];
        __syncthreads();
    }

    // ---- normalize, build O fragments ----
    uint32_t Of[2][4][4];
#pragma unroll
    for (int h = 0; h < 2; h++) {
        float a0 = l0[h], a1 = l1[h];
        a0 += __shfl_xor_sync(0xffffffffu, a0, 1);
        a0 += __shfl_xor_sync(0xffffffffu, a0, 2);
        a1 += __shfl_xor_sync(0xffffffffu, a1, 1);
        a1 += __shfl_xor_sync(0xffffffffu, a1, 2);
        float inv0 = 1.0f / a0, inv1 = 1.0f / a1;
#pragma unroll
        for (int s = 0; s < 4; s++) {
            Of[h][s][0] = pack_bf16(O[h][2 * s][0] * inv0, O[h][2 * s][1] * inv0);
            Of[h][s][1] = pack_bf16(O[h][2 * s][2] * inv1, O[h][2 * s][3] * inv1);
            Of[h][s][2] = pack_bf16(O[h][2 * s + 1][0] * inv0, O[h][2 * s + 1][1] * inv0);
            Of[h][s][3] = pack_bf16(O[h][2 * s + 1][2] * inv1, O[h][2 * s + 1][3] * inv1);
        }
    }

    // ---- out-proj (channel-split: grp 0 -> cc {0,1}, grp 1 -> cc {2,3}) ----
    float* sYa = (float*)(sm + 32768);
    float* sYb = sYa + 4352;
    float* sYg = grp ? sYb : sYa;
    const size_t xoff = (size_t)b * (C1 * HW) + n0;

    for (int r = 0; r < 2; r++) {
        int cc = (grp << 1) + r;
        float Y[2][8][4] = {};
#pragma unroll
        for (int s = 0; s < 4; s++) {
#pragma unroll
            for (int ch = 0; ch < 4; ch++) {
                int rw = (cc << 6) + (ch << 4) + brow;
                int g = (s << 1) + bgsel;
                uint32_t b0, b1, b2, b3;
                ldsm4(b0, b1, b2, b3, sm_u + rw * 128 + ((g ^ (rw & 7)) << 4));
#pragma unroll
                for (int h = 0; h < 2; h++) {
                    mma16816(Y[h][2 * ch], Of[h][s], b0, b1);
                    mma16816(Y[h][2 * ch + 1], Of[h][s], b2, b3);
                }
            }
        }
#pragma unroll
        for (int h = 0; h < 2; h++) {
            int qrow = (qw << 5) + (h << 4) + (lane >> 2);
#pragma unroll
            for (int nt = 0; nt < 8; nt++) {
                int c = (nt << 3) + ((lane & 3) << 1);
                sYg[c * 68 + qrow] = Y[h][nt][0];
                sYg[(c + 1) * 68 + qrow] = Y[h][nt][1];
                sYg[c * 68 + qrow + 8] = Y[h][nt][2];
                sYg[(c + 1) * 68 + qrow + 8] = Y[h][nt][3];
            }
        }
        __syncthreads();
        // store both groups' chunks: channels r*64.. and 128+r*64..
        for (int i2 = tid; i2 < 2048; i2 += 128) {
            int c = i2 >> 4, q4 = (i2 & 15) << 2;
            int chan; const float* ybuf;
            if (c < 64) { chan = (r << 6) + c;            ybuf = sYa + c * 68; }
            else        { chan = 128 + (r << 6) + (c - 64); ybuf = sYb + (c - 64) * 68; }
            size_t g = xoff + (size_t)chan * HW + q4;
            float4 xv = *(const float4*)(x1 + g);
            float4 yv = *(const float4*)(ybuf + q4);
            float bb = bo[chan];
            float4 o;
            o.x = xv.x + yv.x + bb;
            o.y = xv.y + yv.y + bb;
            o.z = xv.z + yv.z + bb;
            o.w = xv.w + yv.w + bb;
            *(float4*)(out + g) = o;
        }
        __syncthreads();
    }
}

extern "C" void kernel_launch(void* const* d_in, const int* in_sizes, int n_in,
                              void* d_out, int out_size) {
    const float* x1 = (const float*)d_in[0];
    const float* x2 = (const float*)d_in[1];
    const float* Wq = (const float*)d_in[2];
    const float* bq = (const float*)d_in[3];
    const float* Wk = (const float*)d_in[4];
    const float* bk = (const float*)d_in[5];
    const float* Wv = (const float*)d_in[6];
    const float* bv = (const float*)d_in[7];
    const float* Wo = (const float*)d_in[8];
    const float* bo = (const float*)d_in[9];
    float* out = (float*)d_out;
    (void)in_sizes; (void)n_in; (void)out_size;

    cudaFuncSetAttribute(attn_kernel, cudaFuncAttributeMaxDynamicSharedMemorySize,
                         SM_ATTN);

    prep_kernel<<<8192 + 384, 256>>>(x2, Wk, Wv, Wq, Wo);
    kvproj_kernel<<<dim3(M / 64, NB), 256>>>(bk, bv);
    qproj_kernel<<<dim3(HW / 64, NB), 256>>>(x1, bq);
    attn_kernel<<<dim3(HW / 64, NB), 128, SM_ATTN>>>(x1, bo, out);
}

// round 10
// speedup vs baseline: 1.0015x; 1.0015x over previous
#include <cuda_runtime.h>
#include <cuda_bf16.h>
#include <cstdint>

#define NB 8
#define C1 256
#define C2 512
#define HW 4096
#define D  64
#define M  1024
#define LOG2E 1.4426950408889634f

// Scratch (device globals: allocation-free rule)
__device__ __align__(16) __nv_bfloat16 g_x2ph[NB * C2 * M];  // pooled x2, bf16
__device__ __align__(16) __nv_bfloat16 g_Qth[NB * D * HW];   // [b][d][n]
__device__ __align__(16) __nv_bfloat16 g_Kth[NB * D * M];    // [b][d][m], pre-scaled by log2e
__device__ __align__(16) __nv_bfloat16 g_Vth[NB * D * M];    // [b][d][m]
__device__ __align__(16) __nv_bfloat16 g_Wkh[D * C2];
__device__ __align__(16) __nv_bfloat16 g_Wvh[D * C2];
__device__ __align__(16) __nv_bfloat16 g_Wqh[D * C1];
__device__ __align__(16) __nv_bfloat16 g_Woh[C1 * D];

__device__ __forceinline__ uint32_t pack_bf16(float a, float b) {
    __nv_bfloat162 h = __floats2bfloat162_rn(a, b);
    return *reinterpret_cast<uint32_t*>(&h);
}
__device__ __forceinline__ float ex2f(float x) {
    float y;
    asm("ex2.approx.f32 %0, %1;" : "=f"(y) : "f"(x));
    return y;
}
__device__ __forceinline__ void ldsm4(uint32_t& r0, uint32_t& r1, uint32_t& r2,
                                      uint32_t& r3, uint32_t addr) {
    asm volatile("ldmatrix.sync.aligned.m8n8.x4.shared.b16 {%0,%1,%2,%3}, [%4];\n"
                 : "=r"(r0), "=r"(r1), "=r"(r2), "=r"(r3) : "r"(addr));
}
__device__ __forceinline__ void ldsm4t(uint32_t& r0, uint32_t& r1, uint32_t& r2,
                                       uint32_t& r3, uint32_t addr) {
    asm volatile("ldmatrix.sync.aligned.m8n8.x4.trans.shared.b16 {%0,%1,%2,%3}, [%4];\n"
                 : "=r"(r0), "=r"(r1), "=r"(r2), "=r"(r3) : "r"(addr));
}
__device__ __forceinline__ void mma16816(float c[4], const uint32_t a[4],
                                         uint32_t b0, uint32_t b1) {
    asm volatile("mma.sync.aligned.m16n8k16.row.col.f32.bf16.bf16.f32 "
                 "{%0,%1,%2,%3}, {%4,%5,%6,%7}, {%8,%9}, {%0,%1,%2,%3};\n"
                 : "+f"(c[0]), "+f"(c[1]), "+f"(c[2]), "+f"(c[3])
                 : "r"(a[0]), "r"(a[1]), "r"(a[2]), "r"(a[3]), "r"(b0), "r"(b1));
}
__device__ __forceinline__ void cp16(uint32_t saddr, const void* g) {
    asm volatile("cp.async.cg.shared.global [%0], [%1], 16;\n" :: "r"(saddr), "l"(g));
}
__device__ __forceinline__ void cp_commit() { asm volatile("cp.async.commit_group;\n"); }
__device__ __forceinline__ void cp_wait0() { asm volatile("cp.async.wait_group 0;\n"); }

// ---------------- kernel A: pool (blocks < 8192) + weight cvt (rest) ----------------
__global__ void prep_kernel(const float* __restrict__ x2,
                            const float* __restrict__ Wk, const float* __restrict__ Wv,
                            const float* __restrict__ Wq, const float* __restrict__ Wo) {
    if (blockIdx.x < 8192) {
        int i = blockIdx.x * 256 + threadIdx.x;
        int j = i & 15, h2 = (i >> 4) & 31, bc = i >> 9;
        const float* s = x2 + ((size_t)bc << 12) + (h2 << 7) + (j << 2);
        float4 f0 = *(const float4*)s;
        float4 f1 = *(const float4*)(s + 64);
        uint32_t p = pack_bf16(0.25f * (f0.x + f0.y + f1.x + f1.y),
                               0.25f * (f0.z + f0.w + f1.z + f1.w));
        *(uint32_t*)(g_x2ph + ((size_t)bc << 10) + (h2 << 5) + (j << 1)) = p;
    } else {
        int i = (blockIdx.x - 8192) * 256 + threadIdx.x;   // 98304 total
        if (i < 32768)      g_Wkh[i] = __float2bfloat16(Wk[i]);
        else if (i < 65536) g_Wvh[i - 32768] = __float2bfloat16(Wv[i - 32768]);
        else if (i < 81920) g_Wqh[i - 65536] = __float2bfloat16(Wq[i - 65536]);
        else                g_Woh[i - 81920] = __float2bfloat16(Wo[i - 81920]);
    }
}

// ---------------- kernel B: K/V projection, 2-stage cp.async pipeline ----------------
__global__ __launch_bounds__(256) void kvproj_kernel(
        const float* __restrict__ bk, const float* __restrict__ bv) {
    __shared__ __align__(16) char smem[49152];  // sX[2][8K] sWk[2][8K] sWv[2][8K]
    const uint32_t s_u = (uint32_t)__cvta_generic_to_shared(smem);

    const int b = blockIdx.y, m0 = blockIdx.x << 6;
    const int tid = threadIdx.x, wid = tid >> 5, lane = tid & 31;
    const int dw = wid & 3, mw = wid >> 2;

    float CK[4][4] = {}, CV[4][4] = {};

    auto issue = [&](int cc, int t) {
        int c0 = cc << 6;
        for (int i = tid; i < 512; i += 256) {
            int r = i >> 3, pos = i & 7;
            uint32_t dst = t * 8192 + r * 128 + ((pos ^ (r & 7)) << 4);
            cp16(s_u + dst,
                 g_x2ph + ((size_t)(b * C2 + c0 + r) << 10) + m0 + (pos << 3));
            cp16(s_u + 16384 + dst, g_Wkh + r * C2 + c0 + (pos << 3));
            cp16(s_u + 32768 + dst, g_Wvh + r * C2 + c0 + (pos << 3));
        }
        cp_commit();
    };

    issue(0, 0);
    for (int cc = 0; cc < 8; cc++) {
        int cur = cc & 1;
        cp_wait0();
        __syncthreads();
        if (cc < 7) issue(cc + 1, cur ^ 1);

        uint32_t sX_u = s_u + cur * 8192;
        uint32_t sWk_u = s_u + 16384 + cur * 8192;
        uint32_t sWv_u = s_u + 32768 + cur * 8192;
#pragma unroll
        for (int ks = 0; ks < 4; ks++) {
            int ar = (dw << 4) + (lane & 15);
            int ag = (ks << 1) + (lane >> 4);
            uint32_t aoff = ar * 128 + ((ag ^ (ar & 7)) << 4);
            uint32_t Ak[4], Av[4];
            ldsm4(Ak[0], Ak[1], Ak[2], Ak[3], sWk_u + aoff);
            ldsm4(Av[0], Av[1], Av[2], Av[3], sWv_u + aoff);
            int krow = (ks << 4) + (lane & 7) + (((lane >> 3) & 1) << 3);
#pragma unroll
            for (int nt = 0; nt < 2; nt++) {
                int ncol = (mw << 5) + (nt << 4) + ((lane >> 4) << 3);
                uint32_t b0, b1, b2, b3;
                ldsm4t(b0, b1, b2, b3,
                       sX_u + krow * 128 + (((ncol >> 3) ^ (krow & 7)) << 4));
                mma16816(CK[2 * nt], Ak, b0, b1);
                mma16816(CK[2 * nt + 1], Ak, b2, b3);
                mma16816(CV[2 * nt], Av, b0, b1);
                mma16816(CV[2 * nt + 1], Av, b2, b3);
            }
        }
    }
    int row0 = (dw << 4) + (lane >> 2);
    float bk0 = bk[row0], bk1 = bk[row0 + 8];
    float bv0 = bv[row0], bv1 = bv[row0 + 8];
    __nv_bfloat16* Kp = g_Kth + ((size_t)b * 64 + row0) * M + m0;
    __nv_bfloat16* Vp = g_Vth + ((size_t)b * 64 + row0) * M + m0;
#pragma unroll
    for (int nt = 0; nt < 2; nt++)
#pragma unroll
        for (int h = 0; h < 2; h++) {
            int ci = 2 * nt + h;
            int ncol = (mw << 5) + (nt << 4) + (h << 3) + ((lane & 3) << 1);
            *(uint32_t*)(Kp + ncol) =
                pack_bf16((CK[ci][0] + bk0) * LOG2E, (CK[ci][1] + bk0) * LOG2E);
            *(uint32_t*)(Kp + (size_t)8 * M + ncol) =
                pack_bf16((CK[ci][2] + bk1) * LOG2E, (CK[ci][3] + bk1) * LOG2E);
            *(uint32_t*)(Vp + ncol) = pack_bf16(CV[ci][0] + bv0, CV[ci][1] + bv0);
            *(uint32_t*)(Vp + (size_t)8 * M + ncol) = pack_bf16(CV[ci][2] + bv1, CV[ci][3] + bv1);
        }
}

// ---------------- kernel C: Q projection, reg-prefetch double buffer ----------------
__global__ __launch_bounds__(256) void qproj_kernel(
        const float* __restrict__ x1, const float* __restrict__ bq) {
    __shared__ __align__(16) char smem[49152];  // sW[4][8K] + sX[2][8K]
    const uint32_t s_u = (uint32_t)__cvta_generic_to_shared(smem);
    const uint32_t sXb_u = s_u + 32768;

    const int b = blockIdx.y, n0 = blockIdx.x << 6;
    const int tid = threadIdx.x, wid = tid >> 5, lane = tid & 31;
    const int dw = wid & 3, mw = wid >> 2;

    for (int i = tid; i < 2048; i += 256) {
        int ch = i >> 9, j = i & 511, r = j >> 3, pos = j & 7;
        cp16(s_u + ch * 8192 + r * 128 + ((pos ^ (r & 7)) << 4),
             g_Wqh + r * C1 + (ch << 6) + (pos << 3));
    }
    cp_commit();

    const int r0 = tid >> 4, p4 = tid & 15;
    const float* xbase = x1 + ((size_t)(b * C1) << 12) + n0 + (p4 << 2);
    float4 f[4];
#pragma unroll
    for (int k = 0; k < 4; k++)
        f[k] = *(const float4*)(xbase + ((size_t)(r0 + 16 * k) << 12));

    float C[4][4] = {};
    const int r7 = r0 & 7;
    const uint32_t sphys = r0 * 128 + (((p4 >> 1) ^ r7) << 4) + ((p4 & 1) << 3);

    for (int cc = 0; cc < 4; cc++) {
        int cur = cc & 1;
        char* xb = smem + 32768 + cur * 8192;
#pragma unroll
        for (int k = 0; k < 4; k++)
            *(uint2*)(xb + sphys + k * 2048) =
                make_uint2(pack_bf16(f[k].x, f[k].y), pack_bf16(f[k].z, f[k].w));
        float4 f2[4];
        if (cc < 3) {
#pragma unroll
            for (int k = 0; k < 4; k++)
                f2[k] = *(const float4*)(xbase +
                         ((size_t)(((cc + 1) << 6) + r0 + 16 * k) << 12));
        }
        if (cc == 0) cp_wait0();
        __syncthreads();

        uint32_t sW_u = s_u + cc * 8192;
        uint32_t sX_u = sXb_u + cur * 8192;
#pragma unroll
        for (int ks = 0; ks < 4; ks++) {
            int ar = (dw << 4) + (lane & 15);
            int ag = (ks << 1) + (lane >> 4);
            uint32_t A[4];
            ldsm4(A[0], A[1], A[2], A[3], sW_u + ar * 128 + ((ag ^ (ar & 7)) << 4));
            int krow = (ks << 4) + (lane & 7) + (((lane >> 3) & 1) << 3);
#pragma unroll
            for (int nt = 0; nt < 2; nt++) {
                int ncol = (mw << 5) + (nt << 4) + ((lane >> 4) << 3);
                uint32_t b0, b1, b2, b3;
                ldsm4t(b0, b1, b2, b3,
                       sX_u + krow * 128 + (((ncol >> 3) ^ (krow & 7)) << 4));
                mma16816(C[2 * nt], A, b0, b1);
                mma16816(C[2 * nt + 1], A, b2, b3);
            }
        }
        if (cc < 3) {
#pragma unroll
            for (int k = 0; k < 4; k++) f[k] = f2[k];
        }
    }
    int row0 = (dw << 4) + (lane >> 2);
    float b0v = bq[row0], b1v = bq[row0 + 8];
    __nv_bfloat16* Qp = g_Qth + ((size_t)b * 64 + row0) * HW + n0;
#pragma unroll
    for (int nt = 0; nt < 2; nt++)
#pragma unroll
        for (int h = 0; h < 2; h++) {
            int ci = 2 * nt + h;
            int ncol = (mw << 5) + (nt << 4) + (h << 3) + ((lane & 3) << 1);
            *(uint32_t*)(Qp + ncol) = pack_bf16(C[ci][0] + b0v, C[ci][1] + b0v);
            *(uint32_t*)(Qp + (size_t)8 * HW + ncol) = pack_bf16(C[ci][2] + b1v, C[ci][3] + b1v);
        }
}

// ---------------- kernel D: key-split attention + out-proj + residual ----------------
// CTA: 64 queries, 4 warps. Warps {0,1}: even key tiles; {2,3}: odd key tiles.
// Each warp: 32 queries (2 m16 frags). 8 loop iterations of a 128-key tile pair.
// Smem (73728 B):
//   stages: stage s at s*32768: [Ke 8K][Ve 8K][Ko 8K][Vo 8K]
//   Q staging at 65536 (8K, [64d][64q])
//   phase B: Wo at [0,32K) (prefetched into stage0 during last iter);
//            sYa at 32768 (64*68*4), sYb at 32768+17408  (also the O-combine bufs)
#define SM_ATTN 73728
__global__ __launch_bounds__(128, 3) void attn_kernel(
        const float* __restrict__ x1, const float* __restrict__ bo,
        float* __restrict__ out) {
    extern __shared__ char sm[];
    const int b = blockIdx.y, n0 = blockIdx.x << 6;
    const int tid = threadIdx.x, wid = tid >> 5, lane = tid & 31;
    const int qw = wid & 1, grp = wid >> 1;
    const uint32_t sm_u = (uint32_t)__cvta_generic_to_shared(sm);

    const __nv_bfloat16* Qg = g_Qth + (size_t)b * 64 * HW + n0;
    const __nv_bfloat16* Kg0 = g_Kth + (size_t)b * 64 * M;
    const __nv_bfloat16* Vg0 = g_Vth + (size_t)b * 64 * M;

    // ---- stage Q [64d][64q] + tile pair 0 into stage 0 ----
    for (int i = tid; i < 512; i += 128) {
        int r = i >> 3, pos = i & 7;
        cp16(sm_u + 65536 + r * 128 + ((pos ^ (r & 7)) << 4),
             Qg + (size_t)r * HW + (pos << 3));
    }
    for (int i = tid; i < 2048; i += 128) {
        int quad = i >> 9, r = (i >> 3) & 63, pos = i & 7;
        uint32_t dst = quad * 8192 + r * 128 + ((pos ^ (r & 7)) << 4);
        const __nv_bfloat16* base = (quad & 1) ? Vg0 : Kg0;
        cp16(sm_u + dst, base + ((quad >> 1) << 6) + (size_t)r * M + (pos << 3));
    }
    cp_commit(); cp_wait0();
    __syncthreads();

    // ---- Q fragments (A-operand), 2 m16 blocks per warp ----
    uint32_t Qf[2][4][4];
#pragma unroll
    for (int h = 0; h < 2; h++) {
        int mcol = (qw << 5) + (h << 4) + (((lane >> 3) & 1) << 3);
#pragma unroll
        for (int s = 0; s < 4; s++) {
            int krow = (s << 4) + (lane & 7) + ((lane >> 4) << 3);
            ldsm4t(Qf[h][s][0], Qf[h][s][1], Qf[h][s][2], Qf[h][s][3],
                   sm_u + 65536 + krow * 128 + (((mcol >> 3) ^ (krow & 7)) << 4));
        }
    }

    float O[2][8][4] = {};
    float l0[2] = {}, l1[2] = {};

    const int brow = (lane & 7) + ((lane >> 4) << 3);
    const int bgsel = (lane >> 3) & 1;
    const int tkrow = (lane & 7) + (((lane >> 3) & 1) << 3);
    const int tnsel = (lane >> 4) << 3;

    for (int it = 0; it < 8; it++) {
        uint32_t cb = sm_u + ((it & 1) << 15) + (grp << 14);   // this group's tile
        // prefetch next pair (or Wo on the last iteration into dead stage 0)
        if (it < 7) {
            uint32_t pb = sm_u + (((it + 1) & 1) << 15);
            int k0 = (it + 1) << 7;
            for (int i = tid; i < 2048; i += 128) {
                int quad = i >> 9, r = (i >> 3) & 63, pos = i & 7;
                uint32_t dst = pb + quad * 8192 + r * 128 + ((pos ^ (r & 7)) << 4);
                const __nv_bfloat16* base = (quad & 1) ? Vg0 : Kg0;
                cp16(dst, base + k0 + ((quad >> 1) << 6) + (size_t)r * M + (pos << 3));
            }
        } else {
            for (int i = tid; i < 2048; i += 128) {
                int rr = i >> 3, pos = i & 7;
                cp16(sm_u + rr * 128 + ((pos ^ (rr & 7)) << 4),
                     g_Woh + rr * 64 + (pos << 3));
            }
        }
        cp_commit();

        // ---- S = Q K^T in two 32-key halves (keeps live S at 32 regs) ----
        uint32_t Pf[2][4][4];
#pragma unroll
        for (int half = 0; half < 2; half++) {
            float S[2][4][4] = {};
#pragma unroll
            for (int s = 0; s < 4; s++) {
                int krow = (s << 4) + tkrow;
                uint32_t rb = cb + krow * 128;
                int r7x = krow & 7;
#pragma unroll
                for (int nh2 = 0; nh2 < 2; nh2++) {
                    int ncol = ((half * 2 + nh2) << 4) + tnsel;
                    uint32_t b0, b1, b2, b3;
                    ldsm4t(b0, b1, b2, b3, rb + (((ncol >> 3) ^ r7x) << 4));
#pragma unroll
                    for (int h = 0; h < 2; h++) {
                        mma16816(S[h][2 * nh2], Qf[h][s], b0, b1);
                        mma16816(S[h][2 * nh2 + 1], Qf[h][s], b2, b3);
                    }
                }
            }
#pragma unroll
            for (int h = 0; h < 2; h++) {
#pragma unroll
                for (int nt = 0; nt < 4; nt++) {
#pragma unroll
                    for (int j = 0; j < 4; j++) S[h][nt][j] = ex2f(S[h][nt][j]);
                    l0[h] += S[h][nt][0] + S[h][nt][1];
                    l1[h] += S[h][nt][2] + S[h][nt][3];
                }
#pragma unroll
                for (int kk = 0; kk < 2; kk++) {
                    Pf[h][half * 2 + kk][0] = pack_bf16(S[h][2 * kk][0], S[h][2 * kk][1]);
                    Pf[h][half * 2 + kk][1] = pack_bf16(S[h][2 * kk][2], S[h][2 * kk][3]);
                    Pf[h][half * 2 + kk][2] = pack_bf16(S[h][2 * kk + 1][0], S[h][2 * kk + 1][1]);
                    Pf[h][half * 2 + kk][3] = pack_bf16(S[h][2 * kk + 1][2], S[h][2 * kk + 1][3]);
                }
            }
        }
        // ---- O += P V ----
        uint32_t vbase = cb + 8192;
#pragma unroll
        for (int kk = 0; kk < 4; kk++) {
#pragma unroll
            for (int dh = 0; dh < 4; dh++) {
                int r = (dh << 4) + brow;
                int g = (kk << 1) + bgsel;
                uint32_t b0, b1, b2, b3;
                ldsm4(b0, b1, b2, b3, vbase + r * 128 + ((g ^ (r & 7)) << 4));
#pragma unroll
                for (int h = 0; h < 2; h++) {
                    mma16816(O[h][2 * dh], Pf[h][kk], b0, b1);
                    mma16816(O[h][2 * dh + 1], Pf[h][kk], b2, b3);
                }
            }
        }
        cp_wait0();
        __syncthreads();
    }

    // ---- combine partial (O, l) across the two key groups ----
    {
        float* cbuf = (float*)(sm + 32768 + grp * 17408) + (tid & 63) * 68;
#pragma unroll
        for (int i = 0; i < 16; i++)
            ((float4*)cbuf)[i] = ((float4*)O)[i];
        cbuf[64] = l0[0]; cbuf[65] = l0[1]; cbuf[66] = l1[0]; cbuf[67] = l1[1];
        __syncthreads();
        const float* obuf = (float*)(sm + 32768 + (grp ^ 1) * 17408) + (tid & 63) * 68;
#pragma unroll
        for (int i = 0; i < 64; i++) ((float*)O)[i] += obuf[i];
        l0[0] += obuf[64]; l0[1] += obuf[65]; l1[0] += obuf[66]; l1[1] += obuf[67];
        __syncthreads();
    }

    // ---- normalize, build O fragments ----
    uint32_t Of[2][4][4];
#pragma unroll
    for (int h = 0; h < 2; h++) {
        float a0 = l0[h], a1 = l1[h];
        a0 += __shfl_xor_sync(0xffffffffu, a0, 1);
        a0 += __shfl_xor_sync(0xffffffffu, a0, 2);
        a1 += __shfl_xor_sync(0xffffffffu, a1, 1);
        a1 += __shfl_xor_sync(0xffffffffu, a1, 2);
        float inv0 = 1.0f / a0, inv1 = 1.0f / a1;
#pragma unroll
        for (int s = 0; s < 4; s++) {
            Of[h][s][0] = pack_bf16(O[h][2 * s][0] * inv0, O[h][2 * s][1] * inv0);
            Of[h][s][1] = pack_bf16(O[h][2 * s][2] * inv1, O[h][2 * s][3] * inv1);
            Of[h][s][2] = pack_bf16(O[h][2 * s + 1][0] * inv0, O[h][2 * s + 1][1] * inv0);
            Of[h][s][3] = pack_bf16(O[h][2 * s + 1][2] * inv1, O[h][2 * s + 1][3] * inv1);
        }
    }

    // ---- out-proj (channel-split: grp 0 -> cc {0,1}, grp 1 -> cc {2,3}) ----
    float* sYa = (float*)(sm + 32768);
    float* sYb = sYa + 4352;
    float* sYg = grp ? sYb : sYa;
    const size_t xoff = (size_t)b * (C1 * HW) + n0;

    for (int r = 0; r < 2; r++) {
        int cc = (grp << 1) + r;
        float Y[2][8][4] = {};
#pragma unroll
        for (int s = 0; s < 4; s++) {
#pragma unroll
            for (int ch = 0; ch < 4; ch++) {
                int rw = (cc << 6) + (ch << 4) + brow;
                int g = (s << 1) + bgsel;
                uint32_t b0, b1, b2, b3;
                ldsm4(b0, b1, b2, b3, sm_u + rw * 128 + ((g ^ (rw & 7)) << 4));
#pragma unroll
                for (int h = 0; h < 2; h++) {
                    mma16816(Y[h][2 * ch], Of[h][s], b0, b1);
                    mma16816(Y[h][2 * ch + 1], Of[h][s], b2, b3);
                }
            }
        }
#pragma unroll
        for (int h = 0; h < 2; h++) {
            int qrow = (qw << 5) + (h << 4) + (lane >> 2);
#pragma unroll
            for (int nt = 0; nt < 8; nt++) {
                int c = (nt << 3) + ((lane & 3) << 1);
                sYg[c * 68 + qrow] = Y[h][nt][0];
                sYg[(c + 1) * 68 + qrow] = Y[h][nt][1];
                sYg[c * 68 + qrow + 8] = Y[h][nt][2];
                sYg[(c + 1) * 68 + qrow + 8] = Y[h][nt][3];
            }
        }
        __syncthreads();
        // store both groups' chunks: channels r*64.. and 128+r*64..
        for (int i2 = tid; i2 < 2048; i2 += 128) {
            int c = i2 >> 4, q4 = (i2 & 15) << 2;
            int chan; const float* ybuf;
            if (c < 64) { chan = (r << 6) + c;            ybuf = sYa + c * 68; }
            else        { chan = 128 + (r << 6) + (c - 64); ybuf = sYb + (c - 64) * 68; }
            size_t g = xoff + (size_t)chan * HW + q4;
            float4 xv = *(const float4*)(x1 + g);
            float4 yv = *(const float4*)(ybuf + q4);
            float bb = bo[chan];
            float4 o;
            o.x = xv.x + yv.x + bb;
            o.y = xv.y + yv.y + bb;
            o.z = xv.z + yv.z + bb;
            o.w = xv.w + yv.w + bb;
            *(float4*)(out + g) = o;
        }
        __syncthreads();
    }
}

extern "C" void kernel_launch(void* const* d_in, const int* in_sizes, int n_in,
                              void* d_out, int out_size) {
    const float* x1 = (const float*)d_in[0];
    const float* x2 = (const float*)d_in[1];
    const float* Wq = (const float*)d_in[2];
    const float* bq = (const float*)d_in[3];
    const float* Wk = (const float*)d_in[4];
    const float* bk = (const float*)d_in[5];
    const float* Wv = (const float*)d_in[6];
    const float* bv = (const float*)d_in[7];
    const float* Wo = (const float*)d_in[8];
    const float* bo = (const float*)d_in[9];
    float* out = (float*)d_out;
    (void)in_sizes; (void)n_in; (void)out_size;

    cudaFuncSetAttribute(attn_kernel, cudaFuncAttributeMaxDynamicSharedMemorySize,
                         SM_ATTN);

    prep_kernel<<<8192 + 384, 256>>>(x2, Wk, Wv, Wq, Wo);
    kvproj_kernel<<<dim3(M / 64, NB), 256>>>(bk, bv);
    qproj_kernel<<<dim3(HW / 64, NB), 256>>>(x1, bq);
    attn_kernel<<<dim3(HW / 64, NB), 128, SM_ATTN>>>(x1, bo, out);
}

// round 12
// speedup vs baseline: 1.2282x; 1.2264x over previous
#include <cuda_runtime.h>
#include <cuda_bf16.h>
#include <cstdint>

#define NB 8
#define C1 256
#define C2 512
#define HW 4096
#define D  64
#define M  1024
#define LDY 132
#define LOG2E 1.4426950408889634f

// Scratch (device globals: allocation-free rule)
__device__ __align__(16) __nv_bfloat16 g_x2ph[NB * C2 * M];  // pooled x2, bf16
__device__ __align__(16) __nv_bfloat16 g_Kth[NB * D * M];    // [b][d][m], pre-scaled log2e
__device__ __align__(16) __nv_bfloat16 g_Vth[NB * D * M];    // [b][d][m]
__device__ __align__(16) __nv_bfloat16 g_Wkh[D * C2];
__device__ __align__(16) __nv_bfloat16 g_Wvh[D * C2];
__device__ __align__(16) __nv_bfloat16 g_Wqh[D * C1];
__device__ __align__(16) __nv_bfloat16 g_Woh[C1 * D];

__device__ __forceinline__ uint32_t pack_bf16(float a, float b) {
    __nv_bfloat162 h = __floats2bfloat162_rn(a, b);
    return *reinterpret_cast<uint32_t*>(&h);
}
__device__ __forceinline__ float ex2f(float x) {
    float y;
    asm("ex2.approx.f32 %0, %1;" : "=f"(y) : "f"(x));
    return y;
}
__device__ __forceinline__ void ldsm4(uint32_t& r0, uint32_t& r1, uint32_t& r2,
                                      uint32_t& r3, uint32_t addr) {
    asm volatile("ldmatrix.sync.aligned.m8n8.x4.shared.b16 {%0,%1,%2,%3}, [%4];\n"
                 : "=r"(r0), "=r"(r1), "=r"(r2), "=r"(r3) : "r"(addr));
}
__device__ __forceinline__ void ldsm4t(uint32_t& r0, uint32_t& r1, uint32_t& r2,
                                       uint32_t& r3, uint32_t addr) {
    asm volatile("ldmatrix.sync.aligned.m8n8.x4.trans.shared.b16 {%0,%1,%2,%3}, [%4];\n"
                 : "=r"(r0), "=r"(r1), "=r"(r2), "=r"(r3) : "r"(addr));
}
__device__ __forceinline__ void mma16816(float c[4], const uint32_t a[4],
                                         uint32_t b0, uint32_t b1) {
    asm volatile("mma.sync.aligned.m16n8k16.row.col.f32.bf16.bf16.f32 "
                 "{%0,%1,%2,%3}, {%4,%5,%6,%7}, {%8,%9}, {%0,%1,%2,%3};\n"
                 : "+f"(c[0]), "+f"(c[1]), "+f"(c[2]), "+f"(c[3])
                 : "r"(a[0]), "r"(a[1]), "r"(a[2]), "r"(a[3]), "r"(b0), "r"(b1));
}
__device__ __forceinline__ void cp16(uint32_t saddr, const void* g) {
    asm volatile("cp.async.cg.shared.global [%0], [%1], 16;\n" :: "r"(saddr), "l"(g));
}
__device__ __forceinline__ void cp_commit() { asm volatile("cp.async.commit_group;\n"); }
__device__ __forceinline__ void cp_wait0() { asm volatile("cp.async.wait_group 0;\n"); }

// ---------------- kernel A: pool (blocks < 8192) + weight cvt (rest) ----------------
__global__ void prep_kernel(const float* __restrict__ x2,
                            const float* __restrict__ Wk, const float* __restrict__ Wv,
                            const float* __restrict__ Wq, const float* __restrict__ Wo) {
    if (blockIdx.x < 8192) {
        int i = blockIdx.x * 256 + threadIdx.x;
        int j = i & 15, h2 = (i >> 4) & 31, bc = i >> 9;
        const float* s = x2 + ((size_t)bc << 12) + (h2 << 7) + (j << 2);
        float4 f0 = *(const float4*)s;
        float4 f1 = *(const float4*)(s + 64);
        uint32_t p = pack_bf16(0.25f * (f0.x + f0.y + f1.x + f1.y),
                               0.25f * (f0.z + f0.w + f1.z + f1.w));
        *(uint32_t*)(g_x2ph + ((size_t)bc << 10) + (h2 << 5) + (j << 1)) = p;
    } else {
        int i = (blockIdx.x - 8192) * 256 + threadIdx.x;   // 98304 total
        if (i < 32768)      g_Wkh[i] = __float2bfloat16(Wk[i]);
        else if (i < 65536) g_Wvh[i - 32768] = __float2bfloat16(Wv[i - 32768]);
        else if (i < 81920) g_Wqh[i - 65536] = __float2bfloat16(Wq[i - 65536]);
        else                g_Woh[i - 81920] = __float2bfloat16(Wo[i - 81920]);
    }
}

// ---------------- kernel B: K/V projection, 2-stage cp.async pipeline ----------------
__global__ __launch_bounds__(256) void kvproj_kernel(
        const float* __restrict__ bk, const float* __restrict__ bv) {
    __shared__ __align__(16) char smem[49152];  // sX[2][8K] sWk[2][8K] sWv[2][8K]
    const uint32_t s_u = (uint32_t)__cvta_generic_to_shared(smem);

    const int b = blockIdx.y, m0 = blockIdx.x << 6;
    const int tid = threadIdx.x, wid = tid >> 5, lane = tid & 31;
    const int dw = wid & 3, mw = wid >> 2;

    float CK[4][4] = {}, CV[4][4] = {};

    auto issue = [&](int cc, int t) {
        int c0 = cc << 6;
        for (int i = tid; i < 512; i += 256) {
            int r = i >> 3, pos = i & 7;
            uint32_t dst = t * 8192 + r * 128 + ((pos ^ (r & 7)) << 4);
            cp16(s_u + dst,
                 g_x2ph + ((size_t)(b * C2 + c0 + r) << 10) + m0 + (pos << 3));
            cp16(s_u + 16384 + dst, g_Wkh + r * C2 + c0 + (pos << 3));
            cp16(s_u + 32768 + dst, g_Wvh + r * C2 + c0 + (pos << 3));
        }
        cp_commit();
    };

    issue(0, 0);
    for (int cc = 0; cc < 8; cc++) {
        int cur = cc & 1;
        cp_wait0();
        __syncthreads();
        if (cc < 7) issue(cc + 1, cur ^ 1);

        uint32_t sX_u = s_u + cur * 8192;
        uint32_t sWk_u = s_u + 16384 + cur * 8192;
        uint32_t sWv_u = s_u + 32768 + cur * 8192;
#pragma unroll
        for (int ks = 0; ks < 4; ks++) {
            int ar = (dw << 4) + (lane & 15);
            int ag = (ks << 1) + (lane >> 4);
            uint32_t aoff = ar * 128 + ((ag ^ (ar & 7)) << 4);
            uint32_t Ak[4], Av[4];
            ldsm4(Ak[0], Ak[1], Ak[2], Ak[3], sWk_u + aoff);
            ldsm4(Av[0], Av[1], Av[2], Av[3], sWv_u + aoff);
            int krow = (ks << 4) + (lane & 7) + (((lane >> 3) & 1) << 3);
#pragma unroll
            for (int nt = 0; nt < 2; nt++) {
                int ncol = (mw << 5) + (nt << 4) + ((lane >> 4) << 3);
                uint32_t b0, b1, b2, b3;
                ldsm4t(b0, b1, b2, b3,
                       sX_u + krow * 128 + (((ncol >> 3) ^ (krow & 7)) << 4));
                mma16816(CK[2 * nt], Ak, b0, b1);
                mma16816(CK[2 * nt + 1], Ak, b2, b3);
                mma16816(CV[2 * nt], Av, b0, b1);
                mma16816(CV[2 * nt + 1], Av, b2, b3);
            }
        }
    }
    int row0 = (dw << 4) + (lane >> 2);
    float bk0 = bk[row0], bk1 = bk[row0 + 8];
    float bv0 = bv[row0], bv1 = bv[row0 + 8];
    __nv_bfloat16* Kp = g_Kth + ((size_t)b * 64 + row0) * M + m0;
    __nv_bfloat16* Vp = g_Vth + ((size_t)b * 64 + row0) * M + m0;
#pragma unroll
    for (int nt = 0; nt < 2; nt++)
#pragma unroll
        for (int h = 0; h < 2; h++) {
            int ci = 2 * nt + h;
            int ncol = (mw << 5) + (nt << 4) + (h << 3) + ((lane & 3) << 1);
            // K pre-scaled by log2e so attention uses raw ex2
            *(uint32_t*)(Kp + ncol) =
                pack_bf16((CK[ci][0] + bk0) * LOG2E, (CK[ci][1] + bk0) * LOG2E);
            *(uint32_t*)(Kp + (size_t)8 * M + ncol) =
                pack_bf16((CK[ci][2] + bk1) * LOG2E, (CK[ci][3] + bk1) * LOG2E);
            *(uint32_t*)(Vp + ncol) = pack_bf16(CV[ci][0] + bv0, CV[ci][1] + bv0);
            *(uint32_t*)(Vp + (size_t)8 * M + ncol) = pack_bf16(CV[ci][2] + bv1, CV[ci][3] + bv1);
        }
}

// ---------------- kernel C: fused Q-proj + attention + out-proj + residual ----------------
// CTA: 128 queries, 4 warps (warp = 32 queries, 2 m16 frags sharing B frags).
// Smem (97 KB total):
//  Phase A (Q-proj): Wq chunks [0,32K); x1 bufs [32K,48K),[48K,64K); Qt [64K,80K)
//  Phase B (attn):   B0 [0,16K), B1 [16K,32K) (8K K + 8K V each);
//                    Wo [32K,64K) (prefetched during tiles 14/15);
//                    sY fp32 at [64K, 64K+33792)  (overlays dead Qt)
#define SM_ATTN 99328
__global__ __launch_bounds__(128, 2) void attn_kernel(
        const float* __restrict__ x1, const float* __restrict__ bq,
        const float* __restrict__ bo, float* __restrict__ out) {
    extern __shared__ char sm[];
    float* sY = (float*)(sm + 65536);

    const int b = blockIdx.y, n0 = blockIdx.x << 7;
    const int tid = threadIdx.x, wid = tid >> 5, lane = tid & 31;
    const uint32_t sm_u = (uint32_t)__cvta_generic_to_shared(sm);

    // ================= Phase A: Q tile = Wq * x1 + bq -> Qt[d][n] smem =================
    // stage all Wq (4 chunks of [64d][64c] bf16) via cp.async
    for (int i = tid; i < 2048; i += 128) {
        int ch = i >> 9, j = i & 511, r = j >> 3, pos = j & 7;
        cp16(sm_u + ch * 8192 + r * 128 + ((pos ^ (r & 7)) << 4),
             g_Wqh + r * C1 + (ch << 6) + (pos << 3));
    }
    cp_commit();

    const int r0 = tid >> 5, p4 = tid & 31;   // r0: base row (stride 4), p4: n-pos (4 floats)
    const float* xbase = x1 + ((size_t)(b * C1) << 12) + n0 + (p4 << 2);
    float4 f[16];
#pragma unroll
    for (int k = 0; k < 16; k++)
        f[k] = *(const float4*)(xbase + ((size_t)(r0 + (k << 2)) << 12));

    float C[16][4] = {};
    for (int cc = 0; cc < 4; cc++) {
        char* xb = sm + 32768 + (cc & 1) * 16384;
#pragma unroll
        for (int k = 0; k < 16; k++) {
            int r = r0 + (k << 2);
            uint32_t ph = r * 256 + (((p4 >> 1) ^ (r & 7)) << 4) + ((p4 & 1) << 3);
            *(uint2*)(xb + ph) =
                make_uint2(pack_bf16(f[k].x, f[k].y), pack_bf16(f[k].z, f[k].w));
        }
        float4 f2[16];
        if (cc < 3) {
#pragma unroll
            for (int k = 0; k < 16; k++)
                f2[k] = *(const float4*)(xbase +
                         ((size_t)(((cc + 1) << 6) + r0 + (k << 2)) << 12));
        }
        if (cc == 0) cp_wait0();
        __syncthreads();

        uint32_t sW_u = sm_u + cc * 8192;
        uint32_t sX_u = sm_u + 32768 + (cc & 1) * 16384;
#pragma unroll
        for (int ks = 0; ks < 4; ks++) {
            int ar = (wid << 4) + (lane & 15);
            int ag = (ks << 1) + (lane >> 4);
            uint32_t A[4];
            ldsm4(A[0], A[1], A[2], A[3], sW_u + ar * 128 + ((ag ^ (ar & 7)) << 4));
            int krow = (ks << 4) + (lane & 7) + (((lane >> 3) & 1) << 3);
#pragma unroll
            for (int nt = 0; nt < 8; nt++) {
                int ncol = (nt << 4) + ((lane >> 4) << 3);
                uint32_t b0, b1, b2, b3;
                ldsm4t(b0, b1, b2, b3,
                       sX_u + krow * 256 + (((ncol >> 3) ^ (krow & 7)) << 4));
                mma16816(C[2 * nt], A, b0, b1);
                mma16816(C[2 * nt + 1], A, b2, b3);
            }
        }
        if (cc < 3) {
#pragma unroll
            for (int k = 0; k < 16; k++) f[k] = f2[k];
        }
    }
    // bias + pack -> Qt [64d][128n] bf16 at 65536 (256B rows, swizzled)
    {
        int rowd = (wid << 4) + (lane >> 2);
        float bq0 = bq[rowd], bq1 = bq[rowd + 8];
        int r1 = rowd + 8;
#pragma unroll
        for (int nt = 0; nt < 8; nt++)
#pragma unroll
            for (int h = 0; h < 2; h++) {
                int ci = 2 * nt + h;
                int ncol = (nt << 4) + (h << 3) + ((lane & 3) << 1);
                *(uint32_t*)(sm + 65536 + rowd * 256 +
                             (((ncol >> 3) ^ (rowd & 7)) << 4) + ((ncol & 7) << 1)) =
                    pack_bf16(C[ci][0] + bq0, C[ci][1] + bq0);
                *(uint32_t*)(sm + 65536 + r1 * 256 +
                             (((ncol >> 3) ^ (r1 & 7)) << 4) + ((ncol & 7) << 1)) =
                    pack_bf16(C[ci][2] + bq1, C[ci][3] + bq1);
            }
    }
    __syncthreads();   // Qt complete; Wq/x1 regions now dead

    // ================= Phase B: attention (round-8 body) =================
    const __nv_bfloat16* Kg0 = g_Kth + (size_t)b * 64 * M;
    const __nv_bfloat16* Vg0 = g_Vth + (size_t)b * 64 * M;

    // stage K/V tile 0 into B1
    for (int i = tid; i < 512; i += 128) {
        int r = i >> 3, pos = i & 7;
        uint32_t sw = ((pos ^ (r & 7)) << 4);
        cp16(sm_u + 16384 + r * 128 + sw, Kg0 + (size_t)r * M + (pos << 3));
        cp16(sm_u + 24576 + r * 128 + sw, Vg0 + (size_t)r * M + (pos << 3));
    }
    cp_commit();

    // Q fragments from Qt via trans-ldmatrix
    uint32_t Qf[2][4][4];
#pragma unroll
    for (int h = 0; h < 2; h++) {
        int mcol = (wid << 5) + (h << 4) + (((lane >> 3) & 1) << 3);
#pragma unroll
        for (int s = 0; s < 4; s++) {
            int krow = (s << 4) + (lane & 7) + ((lane >> 4) << 3);
            ldsm4t(Qf[h][s][0], Qf[h][s][1], Qf[h][s][2], Qf[h][s][3],
                   sm_u + 65536 + krow * 256 + (((mcol >> 3) ^ (krow & 7)) << 4));
        }
    }
    cp_wait0();
    __syncthreads();

    float O[2][8][4] = {};
    float l0[2] = {}, l1[2] = {};

    const int brow = (lane & 7) + ((lane >> 4) << 3);
    const int bgsel = (lane >> 3) & 1;
    const int tkrow = (lane & 7) + (((lane >> 3) & 1) << 3);
    const int tnsel = (lane >> 4) << 3;

    for (int kt = 0; kt < 16; kt++) {
        uint32_t cbase = sm_u + (((kt & 1) ^ 1) << 14);
        if (kt < 15) {
            uint32_t pb = sm_u + ((kt & 1) << 14);
            const __nv_bfloat16* Kg = Kg0 + (kt + 1) * 64;
            const __nv_bfloat16* Vg = Vg0 + (kt + 1) * 64;
            for (int i = tid; i < 512; i += 128) {
                int r = i >> 3, pos = i & 7;
                uint32_t sw = ((pos ^ (r & 7)) << 4);
                cp16(pb + r * 128 + sw, Kg + (size_t)r * M + (pos << 3));
                cp16(pb + 8192 + r * 128 + sw, Vg + (size_t)r * M + (pos << 3));
            }
            if (kt == 14) {
                // Wo rows 0..127 -> [32K,48K)
                for (int i = tid; i < 1024; i += 128) {
                    int r = i >> 3, pos = i & 7;
                    cp16(sm_u + 32768 + r * 128 + ((pos ^ (r & 7)) << 4),
                         g_Woh + r * 64 + (pos << 3));
                }
            }
        } else {
            // Wo rows 128..255 -> [48K,64K)
            for (int i = tid; i < 1024; i += 128) {
                int r = 128 + (i >> 3), pos = i & 7;
                cp16(sm_u + 32768 + r * 128 + ((pos ^ (r & 7)) << 4),
                     g_Woh + r * 64 + (pos << 3));
            }
        }
        cp_commit();

        // S = Q K^T
        float S[2][8][4] = {};
#pragma unroll
        for (int s = 0; s < 4; s++) {
            int krow = (s << 4) + tkrow;
            uint32_t rb = cbase + krow * 128;
            int r7x = (krow & 7);
#pragma unroll
            for (int nh = 0; nh < 4; nh++) {
                int ncol = (nh << 4) + tnsel;
                uint32_t b0, b1, b2, b3;
                ldsm4t(b0, b1, b2, b3, rb + (((ncol >> 3) ^ r7x) << 4));
#pragma unroll
                for (int h = 0; h < 2; h++) {
                    mma16816(S[h][2 * nh], Qf[h][s], b0, b1);
                    mma16816(S[h][2 * nh + 1], Qf[h][s], b2, b3);
                }
            }
        }
        // softmax numerator + pack
        uint32_t Pf[2][4][4];
#pragma unroll
        for (int h = 0; h < 2; h++) {
#pragma unroll
            for (int nt = 0; nt < 8; nt++) {
#pragma unroll
                for (int j = 0; j < 4; j++) S[h][nt][j] = ex2f(S[h][nt][j]);
                l0[h] += S[h][nt][0] + S[h][nt][1];
                l1[h] += S[h][nt][2] + S[h][nt][3];
            }
#pragma unroll
            for (int kk = 0; kk < 4; kk++) {
                Pf[h][kk][0] = pack_bf16(S[h][2 * kk][0], S[h][2 * kk][1]);
                Pf[h][kk][1] = pack_bf16(S[h][2 * kk][2], S[h][2 * kk][3]);
                Pf[h][kk][2] = pack_bf16(S[h][2 * kk + 1][0], S[h][2 * kk + 1][1]);
                Pf[h][kk][3] = pack_bf16(S[h][2 * kk + 1][2], S[h][2 * kk + 1][3]);
            }
        }
        // O += P V
        uint32_t vbase = cbase + 8192;
#pragma unroll
        for (int kk = 0; kk < 4; kk++) {
#pragma unroll
            for (int dh = 0; dh < 4; dh++) {
                int r = (dh << 4) + brow;
                int g = (kk << 1) + bgsel;
                uint32_t b0, b1, b2, b3;
                ldsm4(b0, b1, b2, b3, vbase + r * 128 + ((g ^ (r & 7)) << 4));
#pragma unroll
                for (int h = 0; h < 2; h++) {
                    mma16816(O[h][2 * dh], Pf[h][kk], b0, b1);
                    mma16816(O[h][2 * dh + 1], Pf[h][kk], b2, b3);
                }
            }
        }
        cp_wait0();
        __syncthreads();
    }

    // normalize, build O fragments
    uint32_t Of[2][4][4];
#pragma unroll
    for (int h = 0; h < 2; h++) {
        float a0 = l0[h], a1 = l1[h];
        a0 += __shfl_xor_sync(0xffffffffu, a0, 1);
        a0 += __shfl_xor_sync(0xffffffffu, a0, 2);
        a1 += __shfl_xor_sync(0xffffffffu, a1, 1);
        a1 += __shfl_xor_sync(0xffffffffu, a1, 2);
        float inv0 = 1.0f / a0, inv1 = 1.0f / a1;
#pragma unroll
        for (int s = 0; s < 4; s++) {
            Of[h][s][0] = pack_bf16(O[h][2 * s][0] * inv0, O[h][2 * s][1] * inv0);
            Of[h][s][1] = pack_bf16(O[h][2 * s][2] * inv1, O[h][2 * s][3] * inv1);
            Of[h][s][2] = pack_bf16(O[h][2 * s + 1][0] * inv0, O[h][2 * s + 1][1] * inv0);
            Of[h][s][3] = pack_bf16(O[h][2 * s + 1][2] * inv1, O[h][2 * s + 1][3] * inv1);
        }
    }
    __syncthreads();   // Wo fully resident (last cp_wait0 covered it)

    // out-proj + bias + residual (Wo base 32768)
    const size_t xoff = (size_t)b * (C1 * HW) + n0;
    for (int cc = 0; cc < 4; cc++) {
        float Y[2][8][4] = {};
#pragma unroll
        for (int s = 0; s < 4; s++) {
#pragma unroll
            for (int ch = 0; ch < 4; ch++) {
                int r = (cc << 6) + (ch << 4) + brow;
                int g = (s << 1) + bgsel;
                uint32_t b0, b1, b2, b3;
                ldsm4(b0, b1, b2, b3,
                      sm_u + 32768 + r * 128 + ((g ^ (r & 7)) << 4));
#pragma unroll
                for (int h = 0; h < 2; h++) {
                    mma16816(Y[h][2 * ch], Of[h][s], b0, b1);
                    mma16816(Y[h][2 * ch + 1], Of[h][s], b2, b3);
                }
            }
        }
        if (cc) __syncthreads();
#pragma unroll
        for (int h = 0; h < 2; h++) {
            int qrow = (wid << 5) + (h << 4) + (lane >> 2);
#pragma unroll
            for (int nt = 0; nt < 8; nt++) {
                int c = (nt << 3) + ((lane & 3) << 1);
                sY[c * LDY + qrow] = Y[h][nt][0];
                sY[(c + 1) * LDY + qrow] = Y[h][nt][1];
                sY[c * LDY + qrow + 8] = Y[h][nt][2];
                sY[(c + 1) * LDY + qrow + 8] = Y[h][nt][3];
            }
        }
        __syncthreads();
        for (int i2 = tid; i2 < 2048; i2 += 128) {
            int c = i2 >> 5, q4 = (i2 & 31) << 2;
            size_t gaddr = xoff + (size_t)((cc << 6) + c) * HW + q4;
            float4 xv = *(const float4*)(x1 + gaddr);
            float4 yv = *(const float4*)&sY[c * LDY + q4];
            float bb = bo[(cc << 6) + c];
            float4 o;
            o.x = xv.x + yv.x + bb;
            o.y = xv.y + yv.y + bb;
            o.z = xv.z + yv.z + bb;
            o.w = xv.w + yv.w + bb;
            *(float4*)(out + gaddr) = o;
        }
    }
}

extern "C" void kernel_launch(void* const* d_in, const int* in_sizes, int n_in,
                              void* d_out, int out_size) {
    const float* x1 = (const float*)d_in[0];
    const float* x2 = (const float*)d_in[1];
    const float* Wq = (const float*)d_in[2];
    const float* bq = (const float*)d_in[3];
    const float* Wk = (const float*)d_in[4];
    const float* bk = (const float*)d_in[5];
    const float* Wv = (const float*)d_in[6];
    const float* bv = (const float*)d_in[7];
    const float* Wo = (const float*)d_in[8];
    const float* bo = (const float*)d_in[9];
    float* out = (float*)d_out;
    (void)in_sizes; (void)n_in; (void)out_size;

    cudaFuncSetAttribute(attn_kernel, cudaFuncAttributeMaxDynamicSharedMemorySize,
                         SM_ATTN);

    prep_kernel<<<8192 + 384, 256>>>(x2, Wk, Wv, Wq, Wo);
    kvproj_kernel<<<dim3(M / 64, NB), 256>>>(bk, bv);
    attn_kernel<<<dim3(HW / 128, NB), 128, SM_ATTN>>>(x1, bq, bo, out);
}